// round 4
// baseline (speedup 1.0000x reference)
#include <cuda_runtime.h>
#include <cuda_fp16.h>
#include <cstdint>

// ============================================================================
// out[2048,4096] = x[2048,4096] * W[4096,4096]^T
//   W = dequant_int4(base_packed, scales) + alpha * scatter(COO fp16)
// fp16 operands, fp32 accum via mma.sync.m16n8k16.
// Inputs may arrive canonicalized (uint8->int32, float16->float32); a device-
// side sniffer detects the layout each run.
// ============================================================================

#define O_FEAT 4096
#define I_FEAT 4096
#define M_ROWS 2048

__device__ __align__(256) __half g_A16[M_ROWS * I_FEAT];
__device__ __align__(256) __half g_W16[O_FEAT * I_FEAT];
__device__ int g_pk_fmt;    // 0 = raw uint8 bytes, 1 = int32 (one byte/elem)
__device__ int g_vals_fmt;  // 0 = fp16, 1 = float32

__device__ __forceinline__ uint32_t smem_u32(const void* p) {
    uint32_t a;
    asm("{ .reg .u64 t; cvta.to.shared.u64 t, %1; cvt.u32.u64 %0, t; }"
        : "=r"(a) : "l"(p));
    return a;
}

// ---------------------------------------------------------------------------
// Format sniffer: one block, 1024 threads, ~2us.
// ---------------------------------------------------------------------------
__global__ void sniff_kernel(const void* bp, const void* vals) {
    __shared__ int s_pk_bad;
    __shared__ int s_vf_bad;
    __shared__ int s_vf_maxbits;
    const int tid = threadIdx.x;
    if (tid == 0) { s_pk_bad = 0; s_vf_bad = 0; s_vf_maxbits = 0; }
    __syncthreads();

    // packed: int32-canonicalized iff sampled words all in [0,255]
    const int* pi = (const int*)bp;
#pragma unroll
    for (int i = 0; i < 4; ++i) {
        int v = pi[tid + i * 1024];
        if (v < 0 || v > 255) atomicOr(&s_pk_bad, 1);
    }
    // vals: float32 iff finite and max|v| in [1e-6, 1)
    float f = ((const float*)vals)[tid];
    if (!isfinite(f)) atomicOr(&s_vf_bad, 1);
    else atomicMax(&s_vf_maxbits, __float_as_int(fabsf(f)));
    __syncthreads();

    if (tid == 0) {
        g_pk_fmt = s_pk_bad ? 0 : 1;
        float mx = __int_as_float(s_vf_maxbits);
        g_vals_fmt = (!s_vf_bad && mx > 1e-6f && mx < 1.0f) ? 1 : 0;
    }
}

// ---------------------------------------------------------------------------
// Prep kernels
// ---------------------------------------------------------------------------
__global__ void convert_x_kernel(const float* __restrict__ x) {
    int idx = blockIdx.x * blockDim.x + threadIdx.x;
    if (idx >= M_ROWS * I_FEAT / 8) return;
    const float4* xv = reinterpret_cast<const float4*>(x) + (size_t)idx * 2;
    float4 a = xv[0], b = xv[1];
    __align__(16) __half2 h[4];
    h[0] = __floats2half2_rn(a.x, a.y);
    h[1] = __floats2half2_rn(a.z, a.w);
    h[2] = __floats2half2_rn(b.x, b.y);
    h[3] = __floats2half2_rn(b.z, b.w);
    reinterpret_cast<uint4*>(g_A16)[idx] = *reinterpret_cast<const uint4*>(h);
}

__global__ void dequant_kernel(const void* __restrict__ bp,
                               const float* __restrict__ scales) {
    int idx = blockIdx.x * blockDim.x + threadIdx.x;  // one u32-worth (4 bytes)
    if (idx >= O_FEAT * I_FEAT / 8) return;
    int o = idx >> 9;       // 512 words per row (2048 bytes/row)
    int j = idx & 511;

    unsigned int p;
    if (g_pk_fmt == 0) {
        p = reinterpret_cast<const unsigned int*>(bp)[idx];
    } else {
        const int* pi = reinterpret_cast<const int*>(bp) + (size_t)idx * 4;
        p = (unsigned)(pi[0] & 0xFF) | ((unsigned)(pi[1] & 0xFF) << 8) |
            ((unsigned)(pi[2] & 0xFF) << 16) | ((unsigned)(pi[3] & 0xFF) << 24);
    }
    float s = scales[o];
    __align__(16) __half2 h[4];
#pragma unroll
    for (int b = 0; b < 4; ++b) {
        int q = (p >> (8 * b)) & 0xFF;
        float lo = (float)((q & 0xF) - 8) * s;   // low nibble -> even col
        float hi = (float)((q >> 4) - 8) * s;    // high nibble -> odd col
        h[b] = __floats2half2_rn(lo, hi);
    }
    reinterpret_cast<uint4*>(g_W16 + (size_t)o * I_FEAT + (size_t)j * 8)[0] =
        *reinterpret_cast<const uint4*>(h);
}

__global__ void scatter_kernel(const void* __restrict__ vals,
                               const int* __restrict__ rows,
                               const int* __restrict__ cols,
                               const float* __restrict__ alphap, int nnz) {
    int i = blockIdx.x * blockDim.x + threadIdx.x;
    if (i >= nnz) return;
    float a = 1.0f;
    if (alphap) {
        float f = __ldg(alphap);
        if (isfinite(f) && fabsf(f) > 1e-30f && fabsf(f) < 1e30f) {
            a = f;  // float32 alpha
        } else {
            double d = __ldg(reinterpret_cast<const double*>(alphap));
            a = (float)d;  // float64 alpha (f32 low word reads as 0/denormal)
        }
    }
    float v;
    if (g_vals_fmt == 1) v = reinterpret_cast<const float*>(vals)[i];
    else                 v = __half2float(reinterpret_cast<const __half*>(vals)[i]);
    atomicAdd(g_W16 + (size_t)rows[i] * I_FEAT + cols[i], __float2half(v * a));
}

// ---------------------------------------------------------------------------
// GEMM: CTA tile 128x128, K-chunks of 64 halves (128B rows, XOR swizzle),
// 3-stage cp.async pipeline, 8 warps (2x4), warp tile 64x32, mma.sync f16.
// ---------------------------------------------------------------------------
#define BM 128
#define BN 128
#define BK 64
#define STAGES 3
#define KCHUNKS (I_FEAT / BK)              // 64
#define A_BYTES (BM * 128)                 // 16384
#define B_BYTES (BN * 128)                 // 16384
#define STAGE_BYTES (A_BYTES + B_BYTES)    // 32768
#define SMEM_TOTAL (STAGES * STAGE_BYTES)  // 98304

// swizzled half2 shared load: tile row (128B/row), k = even half index
__device__ __forceinline__ uint32_t lds_h2(uint32_t tile_base, int row, int k) {
    uint32_t byte = (((uint32_t)(k >> 3) ^ ((uint32_t)row & 7u)) << 4) +
                    (((uint32_t)k & 7u) << 1);
    uint32_t v;
    asm volatile("ld.shared.b32 %0, [%1];"
                 : "=r"(v)
                 : "r"(tile_base + (uint32_t)row * 128u + byte));
    return v;
}

__device__ __forceinline__ void mma16816(float* c, const uint32_t* a,
                                         uint32_t b0, uint32_t b1) {
    asm volatile(
        "mma.sync.aligned.m16n8k16.row.col.f32.f16.f16.f32 "
        "{%0,%1,%2,%3}, {%4,%5,%6,%7}, {%8,%9}, {%0,%1,%2,%3};"
        : "+f"(c[0]), "+f"(c[1]), "+f"(c[2]), "+f"(c[3])
        : "r"(a[0]), "r"(a[1]), "r"(a[2]), "r"(a[3]), "r"(b0), "r"(b1));
}

__global__ void __launch_bounds__(256, 1)
gemm_kernel(float* __restrict__ out) {
    extern __shared__ char smem[];
    const uint32_t sbase = smem_u32(smem);
    const int tid = threadIdx.x;
    const int wid = tid >> 5;
    const int lid = tid & 31;
    const int bx = blockIdx.x;   // N tile (0..31)
    const int by = blockIdx.y;   // M tile (0..15)

    const int wm = wid >> 2;     // 0..1  (M: 64 rows)
    const int wn = wid & 3;      // 0..3  (N: 32 cols)

    const __half* gA = g_A16 + (size_t)by * BM * I_FEAT;
    const __half* gB = g_W16 + (size_t)bx * BN * I_FEAT;

    const int qrow = lid >> 2;        // 0..7
    const int qk   = (lid & 3) * 2;   // 0,2,4,6

    float acc[4][4][4];
#pragma unroll
    for (int a = 0; a < 4; ++a)
#pragma unroll
        for (int b = 0; b < 4; ++b)
#pragma unroll
            for (int r = 0; r < 4; ++r) acc[a][b][r] = 0.0f;

#define LOAD_STAGE(s, ch)                                                      \
    do {                                                                       \
        uint32_t aB_ = sbase + (uint32_t)(s) * STAGE_BYTES;                    \
        uint32_t bB_ = aB_ + A_BYTES;                                          \
        _Pragma("unroll")                                                      \
        for (int i_ = 0; i_ < 4; ++i_) {                                       \
            int id_ = tid + i_ * 256;                                          \
            int row_ = id_ >> 3, c_ = id_ & 7;                                 \
            uint32_t sw_ = (uint32_t)(c_ ^ (row_ & 7)) << 4;                   \
            uint32_t da_ = aB_ + (uint32_t)row_ * 128u + sw_;                  \
            const __half* sa_ = gA + (size_t)row_ * I_FEAT + (ch) * BK + c_ * 8; \
            asm volatile("cp.async.cg.shared.global [%0], [%1], 16;"          \
                         :: "r"(da_), "l"(sa_) : "memory");                    \
            uint32_t db_ = bB_ + (uint32_t)row_ * 128u + sw_;                  \
            const __half* sb_ = gB + (size_t)row_ * I_FEAT + (ch) * BK + c_ * 8; \
            asm volatile("cp.async.cg.shared.global [%0], [%1], 16;"          \
                         :: "r"(db_), "l"(sb_) : "memory");                    \
        }                                                                      \
        asm volatile("cp.async.commit_group;" ::: "memory");                   \
    } while (0)

    LOAD_STAGE(0, 0);
    LOAD_STAGE(1, 1);

    int s = 0;
    for (int ch = 0; ch < KCHUNKS; ++ch) {
        if (ch == KCHUNKS - 1) {
            asm volatile("cp.async.wait_group 0;" ::: "memory");
        } else {
            asm volatile("cp.async.wait_group 1;" ::: "memory");
        }
        __syncthreads();

        if (ch + 2 < KCHUNKS) {
            int s2 = s + 2;
            if (s2 >= STAGES) s2 -= STAGES;
            LOAD_STAGE(s2, ch + 2);
        }

        const uint32_t aB = sbase + (uint32_t)s * STAGE_BYTES;
        const uint32_t bB = aB + A_BYTES;

#pragma unroll
        for (int ks = 0; ks < 4; ++ks) {
            const int kb = ks * 16 + qk;
            uint32_t rb[4][2];
#pragma unroll
            for (int nt = 0; nt < 4; ++nt) {
                int r = wn * 32 + nt * 8 + qrow;
                rb[nt][0] = lds_h2(bB, r, kb);
                rb[nt][1] = lds_h2(bB, r, kb + 8);
            }
#pragma unroll
            for (int mt = 0; mt < 4; ++mt) {
                int r = wm * 64 + mt * 16 + qrow;
                uint32_t ra[4];
                ra[0] = lds_h2(aB, r,     kb);
                ra[1] = lds_h2(aB, r + 8, kb);
                ra[2] = lds_h2(aB, r,     kb + 8);
                ra[3] = lds_h2(aB, r + 8, kb + 8);
#pragma unroll
                for (int nt = 0; nt < 4; ++nt)
                    mma16816(acc[mt][nt], ra, rb[nt][0], rb[nt][1]);
            }
        }

        if (++s == STAGES) s = 0;
    }

    const int r0 = lid >> 2;
    const int c0 = (lid & 3) * 2;
#pragma unroll
    for (int mt = 0; mt < 4; ++mt) {
        int m0 = by * BM + wm * 64 + mt * 16 + r0;
#pragma unroll
        for (int nt = 0; nt < 4; ++nt) {
            int n0 = bx * BN + wn * 32 + nt * 8 + c0;
            float2 v0 = make_float2(acc[mt][nt][0], acc[mt][nt][1]);
            float2 v1 = make_float2(acc[mt][nt][2], acc[mt][nt][3]);
            *reinterpret_cast<float2*>(out + (size_t)m0 * O_FEAT + n0) = v0;
            *reinterpret_cast<float2*>(out + (size_t)(m0 + 8) * O_FEAT + n0) = v1;
        }
    }
}

// ---------------------------------------------------------------------------
// kernel_launch
// ---------------------------------------------------------------------------
extern "C" void kernel_launch(void* const* d_in, const int* in_sizes, int n_in,
                              void* d_out, int out_size) {
    const float* x      = (const float*)d_in[0];
    const void*  bp     = d_in[1];
    const float* scales = (const float*)d_in[2];
    const void*  vals   = d_in[3];
    const int*   rows   = (const int*)d_in[4];
    const int*   cols   = (const int*)d_in[5];
    const float* alphap = (n_in > 6) ? (const float*)d_in[6] : nullptr;
    const int nnz = in_sizes[3];

    sniff_kernel<<<1, 1024>>>(bp, vals);
    convert_x_kernel<<<(M_ROWS * I_FEAT / 8 + 255) / 256, 256>>>(x);
    dequant_kernel<<<(O_FEAT * I_FEAT / 8 + 255) / 256, 256>>>(bp, scales);
    scatter_kernel<<<(nnz + 255) / 256, 256>>>(vals, rows, cols, alphap, nnz);

    cudaFuncSetAttribute(gemm_kernel,
                         cudaFuncAttributeMaxDynamicSharedMemorySize, SMEM_TOTAL);
    gemm_kernel<<<dim3(O_FEAT / BN, M_ROWS / BM, 1), 256, SMEM_TOTAL>>>(
        (float*)d_out);
}

// round 5
// speedup vs baseline: 1.0338x; 1.0338x over previous
#include <cuda_runtime.h>
#include <cuda_fp16.h>
#include <cstdint>

// ============================================================================
// out[2048,4096] = x[2048,4096] * W[4096,4096]^T
//   W = dequant_int4(base_packed, scales) + alpha * scatter(COO fp16)
// fp16 operands, fp32 accum via mma.sync.m16n8k16. Inputs may arrive
// canonicalized (uint8->int32, float16->float32); device-side sniffer.
// CTA tile 128x256, warp tile 64x64, ldmatrix.x4 fragments, 3-stage cp.async.
// ============================================================================

#define O_FEAT 4096
#define I_FEAT 4096
#define M_ROWS 2048

__device__ __align__(256) __half g_A16[M_ROWS * I_FEAT];
__device__ __align__(256) __half g_W16[O_FEAT * I_FEAT];
__device__ int g_pk_fmt;    // 0 = raw uint8 bytes, 1 = int32 (one byte/elem)
__device__ int g_vals_fmt;  // 0 = fp16, 1 = float32

__device__ __forceinline__ uint32_t smem_u32(const void* p) {
    uint32_t a;
    asm("{ .reg .u64 t; cvta.to.shared.u64 t, %1; cvt.u32.u64 %0, t; }"
        : "=r"(a) : "l"(p));
    return a;
}

// ---------------------------------------------------------------------------
// Format sniffer
// ---------------------------------------------------------------------------
__global__ void sniff_kernel(const void* bp, const void* vals) {
    __shared__ int s_pk_bad;
    __shared__ int s_vf_bad;
    __shared__ int s_vf_maxbits;
    const int tid = threadIdx.x;
    if (tid == 0) { s_pk_bad = 0; s_vf_bad = 0; s_vf_maxbits = 0; }
    __syncthreads();

    const int* pi = (const int*)bp;
#pragma unroll
    for (int i = 0; i < 4; ++i) {
        int v = pi[tid + i * 1024];
        if (v < 0 || v > 255) atomicOr(&s_pk_bad, 1);
    }
    float f = ((const float*)vals)[tid];
    if (!isfinite(f)) atomicOr(&s_vf_bad, 1);
    else atomicMax(&s_vf_maxbits, __float_as_int(fabsf(f)));
    __syncthreads();

    if (tid == 0) {
        g_pk_fmt = s_pk_bad ? 0 : 1;
        float mx = __int_as_float(s_vf_maxbits);
        g_vals_fmt = (!s_vf_bad && mx > 1e-6f && mx < 1.0f) ? 1 : 0;
    }
}

// ---------------------------------------------------------------------------
// Prep kernels
// ---------------------------------------------------------------------------
__global__ void convert_x_kernel(const float* __restrict__ x) {
    int idx = blockIdx.x * blockDim.x + threadIdx.x;
    if (idx >= M_ROWS * I_FEAT / 8) return;
    const float4* xv = reinterpret_cast<const float4*>(x) + (size_t)idx * 2;
    float4 a = xv[0], b = xv[1];
    __align__(16) __half2 h[4];
    h[0] = __floats2half2_rn(a.x, a.y);
    h[1] = __floats2half2_rn(a.z, a.w);
    h[2] = __floats2half2_rn(b.x, b.y);
    h[3] = __floats2half2_rn(b.z, b.w);
    reinterpret_cast<uint4*>(g_A16)[idx] = *reinterpret_cast<const uint4*>(h);
}

__global__ void dequant_kernel(const void* __restrict__ bp,
                               const float* __restrict__ scales) {
    int idx = blockIdx.x * blockDim.x + threadIdx.x;  // one u32-worth (4 bytes)
    if (idx >= O_FEAT * I_FEAT / 8) return;
    int o = idx >> 9;
    int j = idx & 511;

    unsigned int p;
    if (g_pk_fmt == 0) {
        p = reinterpret_cast<const unsigned int*>(bp)[idx];
    } else {
        const int4 pi = reinterpret_cast<const int4*>(bp)[idx];
        p = (unsigned)(pi.x & 0xFF) | ((unsigned)(pi.y & 0xFF) << 8) |
            ((unsigned)(pi.z & 0xFF) << 16) | ((unsigned)(pi.w & 0xFF) << 24);
    }
    float s = scales[o];
    __align__(16) __half2 h[4];
#pragma unroll
    for (int b = 0; b < 4; ++b) {
        int q = (p >> (8 * b)) & 0xFF;
        float lo = (float)((q & 0xF) - 8) * s;   // low nibble -> even col
        float hi = (float)((q >> 4) - 8) * s;    // high nibble -> odd col
        h[b] = __floats2half2_rn(lo, hi);
    }
    reinterpret_cast<uint4*>(g_W16 + (size_t)o * I_FEAT + (size_t)j * 8)[0] =
        *reinterpret_cast<const uint4*>(h);
}

__device__ __forceinline__ float read_alpha(const float* alphap) {
    float a = 1.0f;
    if (alphap) {
        float f = __ldg(alphap);
        if (isfinite(f) && fabsf(f) > 1e-30f && fabsf(f) < 1e30f) {
            a = f;
        } else {
            double d = __ldg(reinterpret_cast<const double*>(alphap));
            a = (float)d;
        }
    }
    return a;
}

// 4 nnz per thread, vectorized index/value loads
__global__ void scatter_kernel(const void* __restrict__ vals,
                               const int* __restrict__ rows,
                               const int* __restrict__ cols,
                               const float* __restrict__ alphap, int nnz) {
    int t = blockIdx.x * blockDim.x + threadIdx.x;
    int base = t * 4;
    if (base >= nnz) return;
    float a = read_alpha(alphap);

    if (base + 4 <= nnz && g_vals_fmt == 1) {
        int4 r4 = *reinterpret_cast<const int4*>(rows + base);
        int4 c4 = *reinterpret_cast<const int4*>(cols + base);
        float4 v4 = *reinterpret_cast<const float4*>((const float*)vals + base);
        atomicAdd(g_W16 + (size_t)r4.x * I_FEAT + c4.x, __float2half(v4.x * a));
        atomicAdd(g_W16 + (size_t)r4.y * I_FEAT + c4.y, __float2half(v4.y * a));
        atomicAdd(g_W16 + (size_t)r4.z * I_FEAT + c4.z, __float2half(v4.z * a));
        atomicAdd(g_W16 + (size_t)r4.w * I_FEAT + c4.w, __float2half(v4.w * a));
    } else {
        for (int i = base; i < nnz && i < base + 4; ++i) {
            float v;
            if (g_vals_fmt == 1) v = reinterpret_cast<const float*>(vals)[i];
            else v = __half2float(reinterpret_cast<const __half*>(vals)[i]);
            atomicAdd(g_W16 + (size_t)rows[i] * I_FEAT + cols[i],
                      __float2half(v * a));
        }
    }
}

// ---------------------------------------------------------------------------
// GEMM: CTA tile 128x256, K-chunks of 64 halves (128B rows, XOR swizzle),
// 3-stage cp.async pipeline, 8 warps (2x4), warp tile 64x64, ldmatrix.x4.
// ---------------------------------------------------------------------------
#define BM 128
#define BN 256
#define BK 64
#define STAGES 3
#define KCHUNKS (I_FEAT / BK)              // 64
#define A_BYTES (BM * 128)                 // 16384
#define B_BYTES (BN * 128)                 // 32768
#define STAGE_BYTES (A_BYTES + B_BYTES)    // 49152
#define SMEM_TOTAL (STAGES * STAGE_BYTES)  // 147456

__device__ __forceinline__ void ldsm_x4(uint32_t* r, uint32_t addr) {
    asm volatile("ldmatrix.sync.aligned.m8n8.x4.shared.b16 {%0,%1,%2,%3}, [%4];"
                 : "=r"(r[0]), "=r"(r[1]), "=r"(r[2]), "=r"(r[3]) : "r"(addr));
}

__device__ __forceinline__ void mma16816(float* c, const uint32_t* a,
                                         uint32_t b0, uint32_t b1) {
    asm volatile(
        "mma.sync.aligned.m16n8k16.row.col.f32.f16.f16.f32 "
        "{%0,%1,%2,%3}, {%4,%5,%6,%7}, {%8,%9}, {%0,%1,%2,%3};"
        : "+f"(c[0]), "+f"(c[1]), "+f"(c[2]), "+f"(c[3])
        : "r"(a[0]), "r"(a[1]), "r"(a[2]), "r"(a[3]), "r"(b0), "r"(b1));
}

__global__ void __launch_bounds__(256, 1)
gemm_kernel(float* __restrict__ out) {
    extern __shared__ char smem[];
    const uint32_t sbase = smem_u32(smem);
    const int tid = threadIdx.x;
    const int wid = tid >> 5;
    const int lid = tid & 31;
    const int bx = blockIdx.x;   // N tile (0..15)
    const int by = blockIdx.y;   // M tile (0..15)

    const int wm = wid >> 2;     // 0..1  (M: 64 rows)
    const int wn = wid & 3;      // 0..3  (N: 64 cols)

    const __half* gA = g_A16 + (size_t)by * BM * I_FEAT;
    const __half* gB = g_W16 + (size_t)bx * BN * I_FEAT;

    // ldmatrix lane mapping: lanes 0-7 rows 0-7 (k lo), 8-15 rows 8-15 (k lo),
    // 16-23 rows 0-7 (k hi), 24-31 rows 8-15 (k hi)
    const int rlocal = (lid & 7) + ((lid >> 3) & 1) * 8;  // 0..15
    const int csel = lid >> 4;                            // 0/1

    float acc[4][8][4];
#pragma unroll
    for (int a = 0; a < 4; ++a)
#pragma unroll
        for (int b = 0; b < 8; ++b)
#pragma unroll
            for (int r = 0; r < 4; ++r) acc[a][b][r] = 0.0f;

    // Per stage: A = 1024 16B-chunks (4/thread), B = 2048 (8/thread)
#define LOAD_STAGE(s, ch)                                                      \
    do {                                                                       \
        uint32_t aB_ = sbase + (uint32_t)(s) * STAGE_BYTES;                    \
        uint32_t bB_ = aB_ + A_BYTES;                                          \
        _Pragma("unroll")                                                      \
        for (int i_ = 0; i_ < 4; ++i_) {                                       \
            int id_ = tid + i_ * 256;                                          \
            int row_ = id_ >> 3, c_ = id_ & 7;                                 \
            uint32_t sw_ = (uint32_t)(c_ ^ (row_ & 7)) << 4;                   \
            uint32_t da_ = aB_ + (uint32_t)row_ * 128u + sw_;                  \
            const __half* sa_ = gA + (size_t)row_ * I_FEAT + (ch) * BK + c_ * 8; \
            asm volatile("cp.async.cg.shared.global [%0], [%1], 16;"          \
                         :: "r"(da_), "l"(sa_) : "memory");                    \
        }                                                                      \
        _Pragma("unroll")                                                      \
        for (int i_ = 0; i_ < 8; ++i_) {                                       \
            int id_ = tid + i_ * 256;                                          \
            int row_ = id_ >> 3, c_ = id_ & 7;                                 \
            uint32_t sw_ = (uint32_t)(c_ ^ (row_ & 7)) << 4;                   \
            uint32_t db_ = bB_ + (uint32_t)row_ * 128u + sw_;                  \
            const __half* sb_ = gB + (size_t)row_ * I_FEAT + (ch) * BK + c_ * 8; \
            asm volatile("cp.async.cg.shared.global [%0], [%1], 16;"          \
                         :: "r"(db_), "l"(sb_) : "memory");                    \
        }                                                                      \
        asm volatile("cp.async.commit_group;" ::: "memory");                   \
    } while (0)

    LOAD_STAGE(0, 0);
    LOAD_STAGE(1, 1);

    int s = 0;
    for (int ch = 0; ch < KCHUNKS; ++ch) {
        if (ch == KCHUNKS - 1) {
            asm volatile("cp.async.wait_group 0;" ::: "memory");
        } else {
            asm volatile("cp.async.wait_group 1;" ::: "memory");
        }
        __syncthreads();

        if (ch + 2 < KCHUNKS) {
            int s2 = s + 2;
            if (s2 >= STAGES) s2 -= STAGES;
            LOAD_STAGE(s2, ch + 2);
        }

        const uint32_t aB = sbase + (uint32_t)s * STAGE_BYTES;
        const uint32_t bB = aB + A_BYTES;

#pragma unroll
        for (int ks = 0; ks < 4; ++ks) {
            const int kc = ks * 2 + csel;  // 16B chunk within 128B row
            // B fragments: 4 n16-groups, each ldmatrix.x4:
            // reg0 = (n lo8, k lo), reg1 = (n hi8, k lo),
            // reg2 = (n lo8, k hi), reg3 = (n hi8, k hi)
            uint32_t rb[4][4];
#pragma unroll
            for (int nt = 0; nt < 4; ++nt) {
                int row = wn * 64 + nt * 16 + rlocal;
                uint32_t addr = bB + (uint32_t)row * 128u +
                                ((uint32_t)(kc ^ (row & 7)) << 4);
                ldsm_x4(rb[nt], addr);
            }
#pragma unroll
            for (int mt = 0; mt < 4; ++mt) {
                int row = wm * 64 + mt * 16 + rlocal;
                uint32_t addr = aB + (uint32_t)row * 128u +
                                ((uint32_t)(kc ^ (row & 7)) << 4);
                uint32_t ra[4];
                ldsm_x4(ra, addr);
#pragma unroll
                for (int nt = 0; nt < 4; ++nt) {
                    mma16816(acc[mt][2 * nt],     ra, rb[nt][0], rb[nt][2]);
                    mma16816(acc[mt][2 * nt + 1], ra, rb[nt][1], rb[nt][3]);
                }
            }
        }

        if (++s == STAGES) s = 0;
    }

    // epilogue: c0,c1 at (row, col..col+1), c2,c3 at (row+8, col..col+1)
    const int r0 = lid >> 2;
    const int c0 = (lid & 3) * 2;
#pragma unroll
    for (int mt = 0; mt < 4; ++mt) {
        int m0 = by * BM + wm * 64 + mt * 16 + r0;
#pragma unroll
        for (int nf = 0; nf < 8; ++nf) {
            int nt = nf >> 1, hi = nf & 1;
            int n0 = bx * BN + wn * 64 + nt * 16 + hi * 8 + c0;
            float2 v0 = make_float2(acc[mt][nf][0], acc[mt][nf][1]);
            float2 v1 = make_float2(acc[mt][nf][2], acc[mt][nf][3]);
            *reinterpret_cast<float2*>(out + (size_t)m0 * O_FEAT + n0) = v0;
            *reinterpret_cast<float2*>(out + (size_t)(m0 + 8) * O_FEAT + n0) = v1;
        }
    }
}

// ---------------------------------------------------------------------------
// kernel_launch
// ---------------------------------------------------------------------------
extern "C" void kernel_launch(void* const* d_in, const int* in_sizes, int n_in,
                              void* d_out, int out_size) {
    const float* x      = (const float*)d_in[0];
    const void*  bp     = d_in[1];
    const float* scales = (const float*)d_in[2];
    const void*  vals   = d_in[3];
    const int*   rows   = (const int*)d_in[4];
    const int*   cols   = (const int*)d_in[5];
    const float* alphap = (n_in > 6) ? (const float*)d_in[6] : nullptr;
    const int nnz = in_sizes[3];

    sniff_kernel<<<1, 1024>>>(bp, vals);
    convert_x_kernel<<<(M_ROWS * I_FEAT / 8 + 255) / 256, 256>>>(x);
    dequant_kernel<<<(O_FEAT * I_FEAT / 8 + 255) / 256, 256>>>(bp, scales);
    scatter_kernel<<<(nnz / 4 + 255) / 256, 256>>>(vals, rows, cols, alphap, nnz);

    cudaFuncSetAttribute(gemm_kernel,
                         cudaFuncAttributeMaxDynamicSharedMemorySize, SMEM_TOTAL);
    gemm_kernel<<<dim3(O_FEAT / BN, M_ROWS / BM, 1), 256, SMEM_TOTAL>>>(
        (float*)d_out);
}

// round 6
// speedup vs baseline: 1.0877x; 1.0522x over previous
#include <cuda_runtime.h>
#include <cuda_fp16.h>
#include <cstdint>

// ============================================================================
// out[2048,4096] = x[2048,4096] * W[4096,4096]^T
//   W = dequant_int4(base_packed, scales) + alpha * scatter(COO fp16)
// fp16 operands, fp32 accum via mma.sync.m16n8k16.
// Inputs may arrive canonicalized (uint8->int32, float16->float32); format is
// detected from a uniform broadcast load of the leading elements.
// GEMM: 128x128 CTA tile, 2 CTAs/SM, 3-stage cp.async, ldmatrix.x4 fragments.
// ============================================================================

#define O_FEAT 4096
#define I_FEAT 4096
#define M_ROWS 2048

__device__ __align__(256) __half g_A16[M_ROWS * I_FEAT];
__device__ __align__(256) __half g_W16[O_FEAT * I_FEAT];

__device__ __forceinline__ uint32_t smem_u32(const void* p) {
    uint32_t a;
    asm("{ .reg .u64 t; cvta.to.shared.u64 t, %1; cvt.u32.u64 %0, t; }"
        : "=r"(a) : "l"(p));
    return a;
}

// packed int32-canonicalized iff leading 4 words all in [0,255]
// (raw-u8 data reinterpreted hits this with prob ~2^-96; deterministic per run)
__device__ __forceinline__ bool packed_is_int32(const void* bp) {
    int4 w = __ldg(reinterpret_cast<const int4*>(bp));
    return ((unsigned)w.x <= 255u) && ((unsigned)w.y <= 255u) &&
           ((unsigned)w.z <= 255u) && ((unsigned)w.w <= 255u);
}

// vals float32 iff leading 4 f32 are finite with max|v| in (1e-8, 1)
// (fp16 pairs misread as f32 land ~1e-14 or smaller)
__device__ __forceinline__ bool vals_is_f32(const void* vals) {
    float4 v = __ldg(reinterpret_cast<const float4*>(vals));
    float m = fmaxf(fmaxf(fabsf(v.x), fabsf(v.y)), fmaxf(fabsf(v.z), fabsf(v.w)));
    return isfinite(m) && m > 1e-8f && m < 1.0f;
}

__device__ __forceinline__ float read_alpha(const float* alphap) {
    float a = 1.0f;
    if (alphap) {
        float f = __ldg(alphap);
        if (isfinite(f) && fabsf(f) > 1e-30f && fabsf(f) < 1e30f) {
            a = f;  // float32 alpha
        } else {
            double d = __ldg(reinterpret_cast<const double*>(alphap));
            a = (float)d;  // float64 alpha
        }
    }
    return a;
}

// ---------------------------------------------------------------------------
// Fused prep: dequant W (idx < 2M word-groups) + convert x (idx < 1M groups)
// ---------------------------------------------------------------------------
__global__ void prep_kernel(const float* __restrict__ x,
                            const void* __restrict__ bp,
                            const float* __restrict__ scales) {
    const int idx = blockIdx.x * blockDim.x + threadIdx.x;
    const bool pk32 = packed_is_int32(bp);

    if (idx < O_FEAT * I_FEAT / 8) {
        int o = idx >> 9;   // 512 u32-groups per output row
        int j = idx & 511;
        unsigned int p;
        if (pk32) {
            const int4 pi = reinterpret_cast<const int4*>(bp)[idx];
            p = (unsigned)(pi.x & 0xFF) | ((unsigned)(pi.y & 0xFF) << 8) |
                ((unsigned)(pi.z & 0xFF) << 16) | ((unsigned)(pi.w & 0xFF) << 24);
        } else {
            p = reinterpret_cast<const unsigned int*>(bp)[idx];
        }
        float s = scales[o];
        __align__(16) __half2 h[4];
#pragma unroll
        for (int b = 0; b < 4; ++b) {
            int q = (p >> (8 * b)) & 0xFF;
            float lo = (float)((q & 0xF) - 8) * s;   // low nibble -> even col
            float hi = (float)((q >> 4) - 8) * s;    // high nibble -> odd col
            h[b] = __floats2half2_rn(lo, hi);
        }
        reinterpret_cast<uint4*>(g_W16 + (size_t)o * I_FEAT + (size_t)j * 8)[0] =
            *reinterpret_cast<const uint4*>(h);
    }

    if (idx < M_ROWS * I_FEAT / 8) {
        const float4* xv = reinterpret_cast<const float4*>(x) + (size_t)idx * 2;
        float4 a = xv[0], b = xv[1];
        __align__(16) __half2 h[4];
        h[0] = __floats2half2_rn(a.x, a.y);
        h[1] = __floats2half2_rn(a.z, a.w);
        h[2] = __floats2half2_rn(b.x, b.y);
        h[3] = __floats2half2_rn(b.z, b.w);
        reinterpret_cast<uint4*>(g_A16)[idx] = *reinterpret_cast<const uint4*>(h);
    }
}

__global__ void scatter_kernel(const void* __restrict__ vals,
                               const int* __restrict__ rows,
                               const int* __restrict__ cols,
                               const float* __restrict__ alphap, int nnz) {
    int i = blockIdx.x * blockDim.x + threadIdx.x;
    if (i >= nnz) return;
    float a = read_alpha(alphap);
    float v;
    if (vals_is_f32(vals)) v = reinterpret_cast<const float*>(vals)[i];
    else                   v = __half2float(reinterpret_cast<const __half*>(vals)[i]);
    atomicAdd(g_W16 + (size_t)rows[i] * I_FEAT + cols[i], __float2half(v * a));
}

// ---------------------------------------------------------------------------
// GEMM: CTA tile 128x128, K-chunks of 64 halves (128B rows, XOR swizzle),
// 3-stage cp.async pipeline, 8 warps (2x4), warp tile 64x32, ldmatrix.x4.
// 2 CTAs/SM to hide per-chunk barrier/load bubbles.
// ---------------------------------------------------------------------------
#define BM 128
#define BN 128
#define BK 64
#define STAGES 3
#define KCHUNKS (I_FEAT / BK)              // 64
#define A_BYTES (BM * 128)                 // 16384
#define B_BYTES (BN * 128)                 // 16384
#define STAGE_BYTES (A_BYTES + B_BYTES)    // 32768
#define SMEM_TOTAL (STAGES * STAGE_BYTES)  // 98304

__device__ __forceinline__ void ldsm_x4(uint32_t* r, uint32_t addr) {
    asm volatile("ldmatrix.sync.aligned.m8n8.x4.shared.b16 {%0,%1,%2,%3}, [%4];"
                 : "=r"(r[0]), "=r"(r[1]), "=r"(r[2]), "=r"(r[3]) : "r"(addr));
}

__device__ __forceinline__ void mma16816(float* c, const uint32_t* a,
                                         uint32_t b0, uint32_t b1) {
    asm volatile(
        "mma.sync.aligned.m16n8k16.row.col.f32.f16.f16.f32 "
        "{%0,%1,%2,%3}, {%4,%5,%6,%7}, {%8,%9}, {%0,%1,%2,%3};"
        : "+f"(c[0]), "+f"(c[1]), "+f"(c[2]), "+f"(c[3])
        : "r"(a[0]), "r"(a[1]), "r"(a[2]), "r"(a[3]), "r"(b0), "r"(b1));
}

__global__ void __launch_bounds__(256, 2)
gemm_kernel(float* __restrict__ out) {
    extern __shared__ char smem[];
    const uint32_t sbase = smem_u32(smem);
    const int tid = threadIdx.x;
    const int wid = tid >> 5;
    const int lid = tid & 31;
    const int bx = blockIdx.x;   // N tile (0..31)
    const int by = blockIdx.y;   // M tile (0..15)

    const int wm = wid >> 2;     // 0..1  (M: 64 rows)
    const int wn = wid & 3;      // 0..3  (N: 32 cols)

    const __half* gA = g_A16 + (size_t)by * BM * I_FEAT;
    const __half* gB = g_W16 + (size_t)bx * BN * I_FEAT;

    // ldmatrix lane mapping: lanes 0-7 rows 0-7 (k lo), 8-15 rows 8-15 (k lo),
    // 16-23 rows 0-7 (k hi), 24-31 rows 8-15 (k hi)
    const int rlocal = (lid & 7) + ((lid >> 3) & 1) * 8;  // 0..15
    const int csel = lid >> 4;                            // 0/1

    float acc[4][4][4];
#pragma unroll
    for (int a = 0; a < 4; ++a)
#pragma unroll
        for (int b = 0; b < 4; ++b)
#pragma unroll
            for (int r = 0; r < 4; ++r) acc[a][b][r] = 0.0f;

#define LOAD_STAGE(s, ch)                                                      \
    do {                                                                       \
        uint32_t aB_ = sbase + (uint32_t)(s) * STAGE_BYTES;                    \
        uint32_t bB_ = aB_ + A_BYTES;                                          \
        _Pragma("unroll")                                                      \
        for (int i_ = 0; i_ < 4; ++i_) {                                       \
            int id_ = tid + i_ * 256;                                          \
            int row_ = id_ >> 3, c_ = id_ & 7;                                 \
            uint32_t sw_ = (uint32_t)(c_ ^ (row_ & 7)) << 4;                   \
            uint32_t da_ = aB_ + (uint32_t)row_ * 128u + sw_;                  \
            const __half* sa_ = gA + (size_t)row_ * I_FEAT + (ch) * BK + c_ * 8; \
            asm volatile("cp.async.cg.shared.global [%0], [%1], 16;"          \
                         :: "r"(da_), "l"(sa_) : "memory");                    \
            uint32_t db_ = bB_ + (uint32_t)row_ * 128u + sw_;                  \
            const __half* sb_ = gB + (size_t)row_ * I_FEAT + (ch) * BK + c_ * 8; \
            asm volatile("cp.async.cg.shared.global [%0], [%1], 16;"          \
                         :: "r"(db_), "l"(sb_) : "memory");                    \
        }                                                                      \
        asm volatile("cp.async.commit_group;" ::: "memory");                   \
    } while (0)

    LOAD_STAGE(0, 0);
    LOAD_STAGE(1, 1);

    int s = 0;
    for (int ch = 0; ch < KCHUNKS; ++ch) {
        if (ch == KCHUNKS - 1) {
            asm volatile("cp.async.wait_group 0;" ::: "memory");
        } else {
            asm volatile("cp.async.wait_group 1;" ::: "memory");
        }
        __syncthreads();

        if (ch + 2 < KCHUNKS) {
            int s2 = s + 2;
            if (s2 >= STAGES) s2 -= STAGES;
            LOAD_STAGE(s2, ch + 2);
        }

        const uint32_t aB = sbase + (uint32_t)s * STAGE_BYTES;
        const uint32_t bB = aB + A_BYTES;

#pragma unroll
        for (int ks = 0; ks < 4; ++ks) {
            const int kc = ks * 2 + csel;  // 16B chunk within 128B row
            // B fragments: 2 n16-groups; ldsm.x4 regs:
            // reg0=(n lo8,k lo) reg1=(n hi8,k lo) reg2=(n lo8,k hi) reg3=(n hi8,k hi)
            uint32_t rb[2][4];
#pragma unroll
            for (int nt = 0; nt < 2; ++nt) {
                int row = wn * 32 + nt * 16 + rlocal;
                uint32_t addr = bB + (uint32_t)row * 128u +
                                ((uint32_t)(kc ^ (row & 7)) << 4);
                ldsm_x4(rb[nt], addr);
            }
#pragma unroll
            for (int mt = 0; mt < 4; ++mt) {
                int row = wm * 64 + mt * 16 + rlocal;
                uint32_t addr = aB + (uint32_t)row * 128u +
                                ((uint32_t)(kc ^ (row & 7)) << 4);
                uint32_t ra[4];
                ldsm_x4(ra, addr);
#pragma unroll
                for (int nf = 0; nf < 4; ++nf) {
                    int nt = nf >> 1, hi = nf & 1;
                    mma16816(acc[mt][nf], ra, rb[nt][hi], rb[nt][hi + 2]);
                }
            }
        }

        if (++s == STAGES) s = 0;
    }

    // epilogue: c0,c1 at (row, col..col+1), c2,c3 at (row+8, ...)
    const int r0 = lid >> 2;
    const int c0 = (lid & 3) * 2;
#pragma unroll
    for (int mt = 0; mt < 4; ++mt) {
        int m0 = by * BM + wm * 64 + mt * 16 + r0;
#pragma unroll
        for (int nf = 0; nf < 4; ++nf) {
            int nt = nf >> 1, hi = nf & 1;
            int n0 = bx * BN + wn * 32 + nt * 16 + hi * 8 + c0;
            float2 v0 = make_float2(acc[mt][nf][0], acc[mt][nf][1]);
            float2 v1 = make_float2(acc[mt][nf][2], acc[mt][nf][3]);
            *reinterpret_cast<float2*>(out + (size_t)m0 * O_FEAT + n0) = v0;
            *reinterpret_cast<float2*>(out + (size_t)(m0 + 8) * O_FEAT + n0) = v1;
        }
    }
}

// ---------------------------------------------------------------------------
// kernel_launch
// ---------------------------------------------------------------------------
extern "C" void kernel_launch(void* const* d_in, const int* in_sizes, int n_in,
                              void* d_out, int out_size) {
    const float* x      = (const float*)d_in[0];
    const void*  bp     = d_in[1];
    const float* scales = (const float*)d_in[2];
    const void*  vals   = d_in[3];
    const int*   rows   = (const int*)d_in[4];
    const int*   cols   = (const int*)d_in[5];
    const float* alphap = (n_in > 6) ? (const float*)d_in[6] : nullptr;
    const int nnz = in_sizes[3];

    prep_kernel<<<(O_FEAT * I_FEAT / 8 + 255) / 256, 256>>>(x, bp, scales);
    scatter_kernel<<<(nnz + 255) / 256, 256>>>(vals, rows, cols, alphap, nnz);

    cudaFuncSetAttribute(gemm_kernel,
                         cudaFuncAttributeMaxDynamicSharedMemorySize, SMEM_TOTAL);
    gemm_kernel<<<dim3(O_FEAT / BN, M_ROWS / BM, 1), 256, SMEM_TOTAL>>>(
        (float*)d_out);
}

// round 7
// speedup vs baseline: 1.1016x; 1.0127x over previous
#include <cuda_runtime.h>
#include <cuda_fp16.h>
#include <cstdint>

// ============================================================================
// out[2048,4096] = x[2048,4096] * W[4096,4096]^T
//   W = dequant_int4(base_packed, scales) + alpha * scatter(COO fp16)
// fp16 operands, fp32 accum via mma.sync.m16n8k16.
// GEMM: 128x128 CTA tile, 4 warps (warp tile 64x64 -> minimal smem re-reads),
// 2 CTAs/SM, 3-stage cp.async, ldmatrix.x4 fragments.
// ============================================================================

#define O_FEAT 4096
#define I_FEAT 4096
#define M_ROWS 2048

__device__ __align__(256) __half g_A16[M_ROWS * I_FEAT];
__device__ __align__(256) __half g_W16[O_FEAT * I_FEAT];

__device__ __forceinline__ uint32_t smem_u32(const void* p) {
    uint32_t a;
    asm("{ .reg .u64 t; cvta.to.shared.u64 t, %1; cvt.u32.u64 %0, t; }"
        : "=r"(a) : "l"(p));
    return a;
}

// packed int32-canonicalized iff leading 4 words all in [0,255]
__device__ __forceinline__ bool packed_is_int32(const void* bp) {
    int4 w = __ldg(reinterpret_cast<const int4*>(bp));
    return ((unsigned)w.x <= 255u) && ((unsigned)w.y <= 255u) &&
           ((unsigned)w.z <= 255u) && ((unsigned)w.w <= 255u);
}

// vals float32 iff leading 4 f32 are finite with max|v| in (1e-8, 1)
__device__ __forceinline__ bool vals_is_f32(const void* vals) {
    float4 v = __ldg(reinterpret_cast<const float4*>(vals));
    float m = fmaxf(fmaxf(fabsf(v.x), fabsf(v.y)), fmaxf(fabsf(v.z), fabsf(v.w)));
    return isfinite(m) && m > 1e-8f && m < 1.0f;
}

__device__ __forceinline__ float read_alpha(const float* alphap) {
    float a = 1.0f;
    if (alphap) {
        float f = __ldg(alphap);
        if (isfinite(f) && fabsf(f) > 1e-30f && fabsf(f) < 1e30f) {
            a = f;  // float32 alpha
        } else {
            double d = __ldg(reinterpret_cast<const double*>(alphap));
            a = (float)d;  // float64 alpha
        }
    }
    return a;
}

// ---------------------------------------------------------------------------
// Fused prep: dequant W + convert x. Dequant via prmt + fp16 exponent-bias
// magic: bits 0x6400|q encode (1024+q); (v - 1032) * s == (q - 8) * s.
// ---------------------------------------------------------------------------
__global__ void prep_kernel(const float* __restrict__ x,
                            const void* __restrict__ bp,
                            const float* __restrict__ scales) {
    const int idx = blockIdx.x * blockDim.x + threadIdx.x;
    const bool pk32 = packed_is_int32(bp);

    if (idx < O_FEAT * I_FEAT / 8) {
        int o = idx >> 9;   // 512 u32-groups per output row
        int j = idx & 511;
        unsigned int p;
        if (pk32) {
            const int4 pi = reinterpret_cast<const int4*>(bp)[idx];
            p = (unsigned)(pi.x & 0xFF) | ((unsigned)(pi.y & 0xFF) << 8) |
                ((unsigned)(pi.z & 0xFF) << 16) | ((unsigned)(pi.w & 0xFF) << 24);
        } else {
            p = reinterpret_cast<const unsigned int*>(bp)[idx];
        }
        const unsigned lo = p & 0x0F0F0F0Fu;         // low nibbles (even cols)
        const unsigned hi = (p >> 4) & 0x0F0F0F0Fu;  // high nibbles (odd cols)
        const unsigned c1032 = 0x64086408u;          // half2(1032, 1032)
        const __half2 h1032 = *reinterpret_cast<const __half2*>(&c1032);
        const __half2 s2 = __float2half2_rn(scales[o]);

        __align__(16) __half2 h[4];
#pragma unroll
        for (int b = 0; b < 4; ++b) {
            unsigned sel = 0x0400u + (unsigned)b * 0x0101u;  // 0x0400,0x0501,...
            unsigned v = __byte_perm(lo, hi, sel);
            v = (v & 0x000F000Fu) | 0x64006400u;  // half2(1024+lo_b, 1024+hi_b)
            __half2 hv = *reinterpret_cast<const __half2*>(&v);
            h[b] = __hmul2(__hsub2(hv, h1032), s2);
        }
        reinterpret_cast<uint4*>(g_W16 + (size_t)o * I_FEAT + (size_t)j * 8)[0] =
            *reinterpret_cast<const uint4*>(h);
    }

    if (idx < M_ROWS * I_FEAT / 8) {
        const float4* xv = reinterpret_cast<const float4*>(x) + (size_t)idx * 2;
        float4 a = xv[0], b = xv[1];
        __align__(16) __half2 h[4];
        h[0] = __floats2half2_rn(a.x, a.y);
        h[1] = __floats2half2_rn(a.z, a.w);
        h[2] = __floats2half2_rn(b.x, b.y);
        h[3] = __floats2half2_rn(b.z, b.w);
        reinterpret_cast<uint4*>(g_A16)[idx] = *reinterpret_cast<const uint4*>(h);
    }
}

__global__ void scatter_kernel(const void* __restrict__ vals,
                               const int* __restrict__ rows,
                               const int* __restrict__ cols,
                               const float* __restrict__ alphap, int nnz) {
    int i = blockIdx.x * blockDim.x + threadIdx.x;
    if (i >= nnz) return;
    float a = read_alpha(alphap);
    float v;
    if (vals_is_f32(vals)) v = reinterpret_cast<const float*>(vals)[i];
    else                   v = __half2float(reinterpret_cast<const __half*>(vals)[i]);
    atomicAdd(g_W16 + (size_t)rows[i] * I_FEAT + cols[i], __float2half(v * a));
}

// ---------------------------------------------------------------------------
// GEMM: CTA tile 128x128, K-chunks of 64 halves (128B rows, XOR swizzle),
// 3-stage cp.async pipeline, 4 warps (2x2), warp tile 64x64, ldmatrix.x4.
// ---------------------------------------------------------------------------
#define BM 128
#define BN 128
#define BK 64
#define STAGES 3
#define KCHUNKS (I_FEAT / BK)              // 64
#define A_BYTES (BM * 128)                 // 16384
#define B_BYTES (BN * 128)                 // 16384
#define STAGE_BYTES (A_BYTES + B_BYTES)    // 32768
#define SMEM_TOTAL (STAGES * STAGE_BYTES)  // 98304
#define NTHREADS 128

__device__ __forceinline__ void ldsm_x4(uint32_t* r, uint32_t addr) {
    asm volatile("ldmatrix.sync.aligned.m8n8.x4.shared.b16 {%0,%1,%2,%3}, [%4];"
                 : "=r"(r[0]), "=r"(r[1]), "=r"(r[2]), "=r"(r[3]) : "r"(addr));
}

__device__ __forceinline__ void mma16816(float* c, const uint32_t* a,
                                         uint32_t b0, uint32_t b1) {
    asm volatile(
        "mma.sync.aligned.m16n8k16.row.col.f32.f16.f16.f32 "
        "{%0,%1,%2,%3}, {%4,%5,%6,%7}, {%8,%9}, {%0,%1,%2,%3};"
        : "+f"(c[0]), "+f"(c[1]), "+f"(c[2]), "+f"(c[3])
        : "r"(a[0]), "r"(a[1]), "r"(a[2]), "r"(a[3]), "r"(b0), "r"(b1));
}

__global__ void __launch_bounds__(NTHREADS, 2)
gemm_kernel(float* __restrict__ out) {
    extern __shared__ char smem[];
    const uint32_t sbase = smem_u32(smem);
    const int tid = threadIdx.x;
    const int wid = tid >> 5;
    const int lid = tid & 31;
    const int bx = blockIdx.x;   // N tile (0..31)
    const int by = blockIdx.y;   // M tile (0..15)

    const int wm = wid >> 1;     // 0..1  (M: 64 rows)
    const int wn = wid & 1;      // 0..1  (N: 64 cols)

    const __half* gA = g_A16 + (size_t)by * BM * I_FEAT;
    const __half* gB = g_W16 + (size_t)bx * BN * I_FEAT;

    const int rlocal = (lid & 7) + ((lid >> 3) & 1) * 8;  // 0..15
    const int csel = lid >> 4;                            // 0/1

    float acc[4][8][4];
#pragma unroll
    for (int a = 0; a < 4; ++a)
#pragma unroll
        for (int b = 0; b < 8; ++b)
#pragma unroll
            for (int r = 0; r < 4; ++r) acc[a][b][r] = 0.0f;

#define LOAD_STAGE(s, ch)                                                      \
    do {                                                                       \
        uint32_t aB_ = sbase + (uint32_t)(s) * STAGE_BYTES;                    \
        uint32_t bB_ = aB_ + A_BYTES;                                          \
        _Pragma("unroll")                                                      \
        for (int i_ = 0; i_ < 8; ++i_) {                                       \
            int id_ = tid + i_ * NTHREADS;                                     \
            int row_ = id_ >> 3, c_ = id_ & 7;                                 \
            uint32_t sw_ = (uint32_t)(c_ ^ (row_ & 7)) << 4;                   \
            uint32_t da_ = aB_ + (uint32_t)row_ * 128u + sw_;                  \
            const __half* sa_ = gA + (size_t)row_ * I_FEAT + (ch) * BK + c_ * 8; \
            asm volatile("cp.async.cg.shared.global [%0], [%1], 16;"          \
                         :: "r"(da_), "l"(sa_) : "memory");                    \
            uint32_t db_ = bB_ + (uint32_t)row_ * 128u + sw_;                  \
            const __half* sb_ = gB + (size_t)row_ * I_FEAT + (ch) * BK + c_ * 8; \
            asm volatile("cp.async.cg.shared.global [%0], [%1], 16;"          \
                         :: "r"(db_), "l"(sb_) : "memory");                    \
        }                                                                      \
        asm volatile("cp.async.commit_group;" ::: "memory");                   \
    } while (0)

    LOAD_STAGE(0, 0);
    LOAD_STAGE(1, 1);

    int s = 0;
    for (int ch = 0; ch < KCHUNKS; ++ch) {
        if (ch == KCHUNKS - 1) {
            asm volatile("cp.async.wait_group 0;" ::: "memory");
        } else {
            asm volatile("cp.async.wait_group 1;" ::: "memory");
        }
        __syncthreads();

        if (ch + 2 < KCHUNKS) {
            int s2 = s + 2;
            if (s2 >= STAGES) s2 -= STAGES;
            LOAD_STAGE(s2, ch + 2);
        }

        const uint32_t aB = sbase + (uint32_t)s * STAGE_BYTES;
        const uint32_t bB = aB + A_BYTES;

#pragma unroll
        for (int ks = 0; ks < 4; ++ks) {
            const int kc = ks * 2 + csel;
            uint32_t rb[4][4];
#pragma unroll
            for (int nt = 0; nt < 4; ++nt) {
                int row = wn * 64 + nt * 16 + rlocal;
                uint32_t addr = bB + (uint32_t)row * 128u +
                                ((uint32_t)(kc ^ (row & 7)) << 4);
                ldsm_x4(rb[nt], addr);
            }
#pragma unroll
            for (int mt = 0; mt < 4; ++mt) {
                int row = wm * 64 + mt * 16 + rlocal;
                uint32_t addr = aB + (uint32_t)row * 128u +
                                ((uint32_t)(kc ^ (row & 7)) << 4);
                uint32_t ra[4];
                ldsm_x4(ra, addr);
#pragma unroll
                for (int nt = 0; nt < 4; ++nt) {
                    mma16816(acc[mt][2 * nt],     ra, rb[nt][0], rb[nt][2]);
                    mma16816(acc[mt][2 * nt + 1], ra, rb[nt][1], rb[nt][3]);
                }
            }
        }

        if (++s == STAGES) s = 0;
    }

    const int r0 = lid >> 2;
    const int c0 = (lid & 3) * 2;
#pragma unroll
    for (int mt = 0; mt < 4; ++mt) {
        int m0 = by * BM + wm * 64 + mt * 16 + r0;
#pragma unroll
        for (int nf = 0; nf < 8; ++nf) {
            int nt = nf >> 1, hi = nf & 1;
            int n0 = bx * BN + wn * 64 + nt * 16 + hi * 8 + c0;
            float2 v0 = make_float2(acc[mt][nf][0], acc[mt][nf][1]);
            float2 v1 = make_float2(acc[mt][nf][2], acc[mt][nf][3]);
            *reinterpret_cast<float2*>(out + (size_t)m0 * O_FEAT + n0) = v0;
            *reinterpret_cast<float2*>(out + (size_t)(m0 + 8) * O_FEAT + n0) = v1;
        }
    }
}

// ---------------------------------------------------------------------------
// kernel_launch
// ---------------------------------------------------------------------------
extern "C" void kernel_launch(void* const* d_in, const int* in_sizes, int n_in,
                              void* d_out, int out_size) {
    const float* x      = (const float*)d_in[0];
    const void*  bp     = d_in[1];
    const float* scales = (const float*)d_in[2];
    const void*  vals   = d_in[3];
    const int*   rows   = (const int*)d_in[4];
    const int*   cols   = (const int*)d_in[5];
    const float* alphap = (n_in > 6) ? (const float*)d_in[6] : nullptr;
    const int nnz = in_sizes[3];

    prep_kernel<<<(O_FEAT * I_FEAT / 8 + 255) / 256, 256>>>(x, bp, scales);
    scatter_kernel<<<(nnz + 255) / 256, 256>>>(vals, rows, cols, alphap, nnz);

    cudaFuncSetAttribute(gemm_kernel,
                         cudaFuncAttributeMaxDynamicSharedMemorySize, SMEM_TOTAL);
    gemm_kernel<<<dim3(O_FEAT / BN, M_ROWS / BM, 1), NTHREADS, SMEM_TOTAL>>>(
        (float*)d_out);
}